// round 9
// baseline (speedup 1.0000x reference)
#include <cuda_runtime.h>
#include <cuda_fp16.h>
#include <stdint.h>

#define NN 8192
#define NITER 50
#define CSTAR 0.00390625f   /* 2^-8 */
/* decoded K = K_true * 2^-14; r scaled 2^-22, c unscaled (see k_final) */

static __device__ __align__(256) uint32_t g_K8[(size_t)NN * NN / 4];
static __device__ __align__(16) float g_c[(NITER + 1) * NN];  // atomic slices
static __device__ __align__(16) float g_rf[NN];
static __device__ float g_trow[NN];
static __device__ float g_tcol[NN];
static __device__ float g_S1[1];

static __device__ __forceinline__ __half2 u2h(uint32_t x) {
    return *reinterpret_cast<__half2*>(&x);
}
// two e4m3 bytes (sign=0) -> half2 of value*2^-8, exact (incl. subnormals)
static __device__ __forceinline__ __half2 dE(uint32_t q) {  // bytes 0,2
    return u2h((q << 7) & 0x7F807F80u);
}
static __device__ __forceinline__ __half2 dO(uint32_t q) {  // bytes 1,3
    return u2h((q >> 1) & 0x7F807F80u);
}
static __device__ __forceinline__ float ex2f(float x) {
    float r; asm("ex2.approx.f32 %0, %1;" : "=f"(r) : "f"(x)); return r;
}
static __device__ __forceinline__ uint32_t packh2(float a, float b) {
    const uint32_t ua = __half_as_ushort(__float2half_rn(a));
    const uint32_t ub = __half_as_ushort(__float2half_rn(b));
    return ua | (ub << 16);
}

// ---------------------------------------------------------------------------
__global__ void k_init() {
    const int n = (NITER + 1) * NN;   // 417792 == 1632*256
    for (int i = blockIdx.x * blockDim.x + threadIdx.x; i < n;
         i += gridDim.x * blockDim.x) {
        g_c[i] = (i < NN) ? 1.0f : 0.0f;
        if (i < NN) { g_trow[i] = 0.0f; g_tcol[i] = 0.0f; }
        if (i == 0) g_S1[0] = 0.0f;
    }
}

// ---------------------------------------------------------------------------
// fused build + target reductions (unchanged, proven)
// ---------------------------------------------------------------------------
__global__ void __launch_bounds__(256) k_bt(const float* __restrict__ M,
                                            const float* __restrict__ tgt) {
    const int r0 = blockIdx.y << 7;
    const int c0 = blockIdx.x << 10;
    const int t  = threadIdx.x;
    const int lane = t & 31;
    const float4* __restrict__ pm =
        (const float4*)(M + (size_t)r0 * NN + c0) + t;
    const float4* __restrict__ pt =
        (const float4*)(tgt + (size_t)r0 * NN + c0) + t;
    uint32_t* __restrict__ pk = g_K8 + (size_t)r0 * (NN / 4) + (c0 >> 2) + t;

    float cx = 0.f, cy = 0.f, cz = 0.f, cw = 0.f, dot = 0.f;
    for (int r = 0; r < 128; r++) {
        const float4 m4 = pm[r * (NN / 4)];
        const float4 t4 = pt[r * (NN / 4)];
        const float e0 = ex2f(fmaf(14.42695041f, m4.x, -6.0f));
        const float e1 = ex2f(fmaf(14.42695041f, m4.y, -6.0f));
        const float e2 = ex2f(fmaf(14.42695041f, m4.z, -6.0f));
        const float e3 = ex2f(fmaf(14.42695041f, m4.w, -6.0f));
        unsigned short lo, hi;
        asm("cvt.rn.satfinite.e4m3x2.f32 %0, %1, %2;" : "=h"(lo) : "f"(e1), "f"(e0));
        asm("cvt.rn.satfinite.e4m3x2.f32 %0, %1, %2;" : "=h"(hi) : "f"(e3), "f"(e2));
        pk[r * (NN / 4)] = (uint32_t)lo | ((uint32_t)hi << 16);

        cx += t4.x; cy += t4.y; cz += t4.z; cw += t4.w;
        dot = fmaf(t4.x, m4.x, dot);
        dot = fmaf(t4.y, m4.y, dot);
        dot = fmaf(t4.z, m4.z, dot);
        dot = fmaf(t4.w, m4.w, dot);
        float s4 = (t4.x + t4.y) + (t4.z + t4.w);
#pragma unroll
        for (int o = 16; o; o >>= 1)
            s4 += __shfl_xor_sync(0xFFFFFFFFu, s4, o);
        if (lane == 0) atomicAdd(&g_trow[r0 + r], s4);
    }
    float* tc = g_tcol + c0 + (t << 2);
    atomicAdd(tc + 0, cx);
    atomicAdd(tc + 1, cy);
    atomicAdd(tc + 2, cz);
    atomicAdd(tc + 3, cw);

    __shared__ float sred[256];
    sred[t] = dot;
    __syncthreads();
    for (int s = 128; s > 0; s >>= 1) {
        if (t < s) sred[t] += sred[t + s];
        __syncthreads();
    }
    if (t == 0) atomicAdd(&g_S1[0], sred[0]);
}

// ---------------------------------------------------------------------------
// two-row dot sweep over full 8192 cols (R7 pattern, proven)
// ---------------------------------------------------------------------------
static __device__ __forceinline__ void sweep2(
    const uint4* __restrict__ base, const uint4* __restrict__ swv,
    float& va, float& vb)
{
    const uint4* pa = base;
    const uint4* pb = base + (NN / 16);
    const __half2 z = __floats2half2_rn(0.f, 0.f);
    __half2 aE0 = z, aO0 = z, aE1 = z, aO1 = z;
    __half2 bE0 = z, bO0 = z, bE1 = z, bO1 = z;

#pragma unroll 2
    for (int s = 0; s < 16; s += 4) {
        uint4 qa[4], qb[4];
#pragma unroll
        for (int j = 0; j < 4; j++) {
            qa[j] = pa[(s + j) * 32];
            qb[j] = pb[(s + j) * 32];
        }
#pragma unroll
        for (int j = 0; j < 4; j++) {
            const uint4 w0 = swv[(s + j) << 6];
            const uint4 w1 = swv[((s + j) << 6) + 1];
            aE0 = __hfma2(dE(qa[j].x), u2h(w0.x), aE0);
            aO0 = __hfma2(dO(qa[j].x), u2h(w0.y), aO0);
            aE1 = __hfma2(dE(qa[j].y), u2h(w0.z), aE1);
            aO1 = __hfma2(dO(qa[j].y), u2h(w0.w), aO1);
            aE0 = __hfma2(dE(qa[j].z), u2h(w1.x), aE0);
            aO0 = __hfma2(dO(qa[j].z), u2h(w1.y), aO0);
            aE1 = __hfma2(dE(qa[j].w), u2h(w1.z), aE1);
            aO1 = __hfma2(dO(qa[j].w), u2h(w1.w), aO1);
            bE0 = __hfma2(dE(qb[j].x), u2h(w0.x), bE0);
            bO0 = __hfma2(dO(qb[j].x), u2h(w0.y), bO0);
            bE1 = __hfma2(dE(qb[j].y), u2h(w0.z), bE1);
            bO1 = __hfma2(dO(qb[j].y), u2h(w0.w), bO1);
            bE0 = __hfma2(dE(qb[j].z), u2h(w1.x), bE0);
            bO0 = __hfma2(dO(qb[j].z), u2h(w1.y), bO0);
            bE1 = __hfma2(dE(qb[j].w), u2h(w1.z), bE1);
            bO1 = __hfma2(dO(qb[j].w), u2h(w1.w), bO1);
        }
    }
    __half2 sa = __hadd2(__hadd2(aE0, aO0), __hadd2(aE1, aO1));
    __half2 sb = __hadd2(__hadd2(bE0, bO0), __hadd2(bE1, bO1));
    va = __low2float(sa) + __high2float(sa);
    vb = __low2float(sb) + __high2float(sb);
#pragma unroll
    for (int o = 16; o; o >>= 1) {
        va += __shfl_xor_sync(0xFFFFFFFFu, va, o);
        vb += __shfl_xor_sync(0xFFFFFFFFu, vb, o);
    }
}

// ---------------------------------------------------------------------------
// fused iteration: block b owns rows [16b, 16b+16).
// Phase A: row dots r = K wc  (wr kept in smem, r stored only for k_final).
// Phase B: re-read own 16 rows (L2-hot) -> column partials * wr -> atomics
// into the zeroed c_k slice. K is read from DRAM once per iteration.
// ---------------------------------------------------------------------------
__global__ void __launch_bounds__(256, 3) k_iter(const float* __restrict__ cprev,
                                                 float* __restrict__ cnext) {
    __shared__ uint32_t swc[4096];   // 8192 col weights, pair-shuffled half2
    __shared__ uint32_t swr[16];     // 16 row weights, broadcast half2
    const int t = threadIdx.x, w = t >> 5, lane = t & 31;
    const int row0 = blockIdx.x << 4;

    // prologue: wc = CSTAR / c_{k-1}
#pragma unroll
    for (int j = 0; j < 8; j++) {
        const int g = t + (j << 8);
        const float4 c4 = *(const float4*)(cprev + (g << 2));
        swc[2 * g]     = packh2(__fdividef(CSTAR, c4.x), __fdividef(CSTAR, c4.z));
        swc[2 * g + 1] = packh2(__fdividef(CSTAR, c4.y), __fdividef(CSTAR, c4.w));
    }
    __syncthreads();

    // phase A: warp w -> rows row0+2w, row0+2w+1
    {
        const int rowa = row0 + (w << 1);
        const uint4* base = ((const uint4*)g_K8) + (size_t)rowa * (NN / 16) + lane;
        const uint4* swv  = ((const uint4*)swc) + (lane << 1);
        float va, vb;
        sweep2(base, swv, va, vb);
        if (lane == 0) {
            g_rf[rowa]     = va;
            g_rf[rowa + 1] = vb;
            const float wa = __fdividef(CSTAR, va);
            const float wb = __fdividef(CSTAR, vb);
            swr[(w << 1)]     = packh2(wa, wa);
            swr[(w << 1) + 1] = packh2(wb, wb);
        }
    }
    __syncthreads();

    // phase B: two uint4 column chunks per thread, 16 rows each (L2-hot)
#pragma unroll
    for (int h = 0; h < 2; h++) {
        const int cc = t + (h << 8);             // uint4 chunk index 0..511
        const uint4* src = ((const uint4*)g_K8) + (size_t)row0 * (NN / 16) + cc;
        const __half2 z = __floats2half2_rn(0.f, 0.f);
        __half2 A0 = z, A1 = z, A2 = z, A3 = z;
        __half2 A4 = z, A5 = z, A6 = z, A7 = z;
#pragma unroll
        for (int rb = 0; rb < 16; rb += 8) {
            uint4 q[8];
#pragma unroll
            for (int j = 0; j < 8; j++)
                q[j] = src[(size_t)(rb + j) * (NN / 16)];
#pragma unroll
            for (int j = 0; j < 8; j++) {
                const __half2 wr = u2h(swr[rb + j]);
                A0 = __hfma2(dE(q[j].x), wr, A0);
                A1 = __hfma2(dO(q[j].x), wr, A1);
                A2 = __hfma2(dE(q[j].y), wr, A2);
                A3 = __hfma2(dO(q[j].y), wr, A3);
                A4 = __hfma2(dE(q[j].z), wr, A4);
                A5 = __hfma2(dO(q[j].z), wr, A5);
                A6 = __hfma2(dE(q[j].w), wr, A6);
                A7 = __hfma2(dO(q[j].w), wr, A7);
            }
        }
        float* vo = cnext + (cc << 4);
        atomicAdd(vo + 0,  __low2float(A0));
        atomicAdd(vo + 2,  __high2float(A0));
        atomicAdd(vo + 1,  __low2float(A1));
        atomicAdd(vo + 3,  __high2float(A1));
        atomicAdd(vo + 4,  __low2float(A2));
        atomicAdd(vo + 6,  __high2float(A2));
        atomicAdd(vo + 5,  __low2float(A3));
        atomicAdd(vo + 7,  __high2float(A3));
        atomicAdd(vo + 8,  __low2float(A4));
        atomicAdd(vo + 10, __high2float(A4));
        atomicAdd(vo + 9,  __low2float(A5));
        atomicAdd(vo + 11, __high2float(A5));
        atomicAdd(vo + 12, __low2float(A6));
        atomicAdd(vo + 14, __high2float(A6));
        atomicAdd(vo + 13, __low2float(A7));
        atomicAdd(vo + 15, __high2float(A7));
    }
}

// ---------------------------------------------------------------------------
// loss = -10*S1 + 35*ln2*S3 + <trow, ln r50> + <tcol, ln c50>
// ---------------------------------------------------------------------------
__global__ void __launch_bounds__(1024) k_final(float* __restrict__ out) {
    const int t = threadIdx.x;
    const float* cfin = g_c + (size_t)NITER * NN;
    float s1 = 0.f, s2 = 0.f, s3 = 0.f;
    for (int i = t; i < NN; i += 1024) {
        const float tr = g_trow[i];
        s1 += tr * __logf(g_rf[i]);
        s3 += tr;
        s2 += g_tcol[i] * __logf(cfin[i]);
    }
    __shared__ float sa[1024], sb[1024], sc[1024];
    sa[t] = s1; sb[t] = s2; sc[t] = s3;
    __syncthreads();
    for (int s = 512; s > 0; s >>= 1) {
        if (t < s) { sa[t] += sa[t + s]; sb[t] += sb[t + s]; sc[t] += sc[t + s]; }
        __syncthreads();
    }
    if (t == 0)
        out[0] = -10.0f * g_S1[0] + 24.260151319598086f * sc[0] + sa[0] + sb[0];
}

// ---------------------------------------------------------------------------
extern "C" void kernel_launch(void* const* d_in, const int* in_sizes, int n_in,
                              void* d_out, int out_size) {
    (void)in_sizes; (void)n_in; (void)out_size;
    const float* M   = (const float*)d_in[0];
    const float* tgt = (const float*)d_in[1];
    float* out = (float*)d_out;

    void* pC;
    cudaGetSymbolAddress(&pC, g_c);
    float* C = (float*)pC;

    k_init<<<1632, 256>>>();
    k_bt<<<dim3(8, 64), 256>>>(M, tgt);

    for (int k = 1; k <= NITER; k++) {
        k_iter<<<512, 256>>>(C + (size_t)(k - 1) * NN, C + (size_t)k * NN);
    }
    k_final<<<1, 1024>>>(out);
}

// round 10
// speedup vs baseline: 2.5863x; 2.5863x over previous
#include <cuda_runtime.h>
#include <cuda_fp16.h>
#include <stdint.h>

#define NN 8192
#define NITER 50
#define CSTAR 0.00390625f   /* 2^-8 */
/* decoded K = K_true * 2^-14; r scaled 2^-22, c unscaled (see k_final) */

static __device__ __align__(256) uint32_t g_K8[(size_t)NN * NN / 4];
static __device__ __align__(16) float g_c[(NITER + 1) * NN];  // atomic slices
static __device__ __align__(16) float g_rf[NN];
static __device__ float g_trow[NN];
static __device__ float g_tcol[NN];
static __device__ float g_S1[1];

static __device__ __forceinline__ __half2 u2h(uint32_t x) {
    return *reinterpret_cast<__half2*>(&x);
}
// two e4m3 bytes (sign=0) -> half2 of value*2^-8, exact (incl. subnormals)
static __device__ __forceinline__ __half2 dE(uint32_t q) {  // bytes 0,2
    return u2h((q << 7) & 0x7F807F80u);
}
static __device__ __forceinline__ __half2 dO(uint32_t q) {  // bytes 1,3
    return u2h((q >> 1) & 0x7F807F80u);
}
static __device__ __forceinline__ float ex2f(float x) {
    float r; asm("ex2.approx.f32 %0, %1;" : "=f"(r) : "f"(x)); return r;
}
static __device__ __forceinline__ uint32_t packh2(float a, float b) {
    const uint32_t ua = __half_as_ushort(__float2half_rn(a));
    const uint32_t ub = __half_as_ushort(__float2half_rn(b));
    return ua | (ub << 16);
}

// ---------------------------------------------------------------------------
__global__ void k_init() {
    const int n = (NITER + 1) * NN;   // 417792 == 1632*256
    for (int i = blockIdx.x * blockDim.x + threadIdx.x; i < n;
         i += gridDim.x * blockDim.x) {
        g_c[i] = (i < NN) ? 1.0f : 0.0f;
        if (i < NN) { g_trow[i] = 0.0f; g_tcol[i] = 0.0f; }
        if (i == 0) g_S1[0] = 0.0f;
    }
}

// ---------------------------------------------------------------------------
// fused build + target reductions (proven)
// ---------------------------------------------------------------------------
__global__ void __launch_bounds__(256) k_bt(const float* __restrict__ M,
                                            const float* __restrict__ tgt) {
    const int r0 = blockIdx.y << 7;
    const int c0 = blockIdx.x << 10;
    const int t  = threadIdx.x;
    const int lane = t & 31;
    const float4* __restrict__ pm =
        (const float4*)(M + (size_t)r0 * NN + c0) + t;
    const float4* __restrict__ pt =
        (const float4*)(tgt + (size_t)r0 * NN + c0) + t;
    uint32_t* __restrict__ pk = g_K8 + (size_t)r0 * (NN / 4) + (c0 >> 2) + t;

    float cx = 0.f, cy = 0.f, cz = 0.f, cw = 0.f, dot = 0.f;
    for (int r = 0; r < 128; r++) {
        const float4 m4 = pm[r * (NN / 4)];
        const float4 t4 = pt[r * (NN / 4)];
        const float e0 = ex2f(fmaf(14.42695041f, m4.x, -6.0f));
        const float e1 = ex2f(fmaf(14.42695041f, m4.y, -6.0f));
        const float e2 = ex2f(fmaf(14.42695041f, m4.z, -6.0f));
        const float e3 = ex2f(fmaf(14.42695041f, m4.w, -6.0f));
        unsigned short lo, hi;
        asm("cvt.rn.satfinite.e4m3x2.f32 %0, %1, %2;" : "=h"(lo) : "f"(e1), "f"(e0));
        asm("cvt.rn.satfinite.e4m3x2.f32 %0, %1, %2;" : "=h"(hi) : "f"(e3), "f"(e2));
        pk[r * (NN / 4)] = (uint32_t)lo | ((uint32_t)hi << 16);

        cx += t4.x; cy += t4.y; cz += t4.z; cw += t4.w;
        dot = fmaf(t4.x, m4.x, dot);
        dot = fmaf(t4.y, m4.y, dot);
        dot = fmaf(t4.z, m4.z, dot);
        dot = fmaf(t4.w, m4.w, dot);
        float s4 = (t4.x + t4.y) + (t4.z + t4.w);
#pragma unroll
        for (int o = 16; o; o >>= 1)
            s4 += __shfl_xor_sync(0xFFFFFFFFu, s4, o);
        if (lane == 0) atomicAdd(&g_trow[r0 + r], s4);
    }
    float* tc = g_tcol + c0 + (t << 2);
    atomicAdd(tc + 0, cx);
    atomicAdd(tc + 1, cy);
    atomicAdd(tc + 2, cz);
    atomicAdd(tc + 3, cw);

    __shared__ float sred[256];
    sred[t] = dot;
    __syncthreads();
    for (int s = 128; s > 0; s >>= 1) {
        if (t < s) sred[t] += sred[t + s];
        __syncthreads();
    }
    if (t == 0) atomicAdd(&g_S1[0], sred[0]);
}

// ---------------------------------------------------------------------------
// two-row dot sweep over full 8192 cols (R7 pattern, proven)
// ---------------------------------------------------------------------------
static __device__ __forceinline__ void sweep2(
    const uint4* __restrict__ base, const uint4* __restrict__ swv,
    float& va, float& vb)
{
    const uint4* pa = base;
    const uint4* pb = base + (NN / 16);
    const __half2 z = __floats2half2_rn(0.f, 0.f);
    __half2 aE0 = z, aO0 = z, aE1 = z, aO1 = z;
    __half2 bE0 = z, bO0 = z, bE1 = z, bO1 = z;

#pragma unroll 2
    for (int s = 0; s < 16; s += 4) {
        uint4 qa[4], qb[4];
#pragma unroll
        for (int j = 0; j < 4; j++) {
            qa[j] = pa[(s + j) * 32];
            qb[j] = pb[(s + j) * 32];
        }
#pragma unroll
        for (int j = 0; j < 4; j++) {
            const uint4 w0 = swv[(s + j) << 6];
            const uint4 w1 = swv[((s + j) << 6) + 1];
            aE0 = __hfma2(dE(qa[j].x), u2h(w0.x), aE0);
            aO0 = __hfma2(dO(qa[j].x), u2h(w0.y), aO0);
            aE1 = __hfma2(dE(qa[j].y), u2h(w0.z), aE1);
            aO1 = __hfma2(dO(qa[j].y), u2h(w0.w), aO1);
            aE0 = __hfma2(dE(qa[j].z), u2h(w1.x), aE0);
            aO0 = __hfma2(dO(qa[j].z), u2h(w1.y), aO0);
            aE1 = __hfma2(dE(qa[j].w), u2h(w1.z), aE1);
            aO1 = __hfma2(dO(qa[j].w), u2h(w1.w), aO1);
            bE0 = __hfma2(dE(qb[j].x), u2h(w0.x), bE0);
            bO0 = __hfma2(dO(qb[j].x), u2h(w0.y), bO0);
            bE1 = __hfma2(dE(qb[j].y), u2h(w0.z), bE1);
            bO1 = __hfma2(dO(qb[j].y), u2h(w0.w), bO1);
            bE0 = __hfma2(dE(qb[j].z), u2h(w1.x), bE0);
            bO0 = __hfma2(dO(qb[j].z), u2h(w1.y), bO0);
            bE1 = __hfma2(dE(qb[j].w), u2h(w1.z), bE1);
            bO1 = __hfma2(dO(qb[j].w), u2h(w1.w), bO1);
        }
    }
    __half2 sa = __hadd2(__hadd2(aE0, aO0), __hadd2(aE1, aO1));
    __half2 sb = __hadd2(__hadd2(bE0, bO0), __hadd2(bE1, bO1));
    va = __low2float(sa) + __high2float(sa);
    vb = __low2float(sb) + __high2float(sb);
#pragma unroll
    for (int o = 16; o; o >>= 1) {
        va += __shfl_xor_sync(0xFFFFFFFFu, va, o);
        vb += __shfl_xor_sync(0xFFFFFFFFu, vb, o);
    }
}

// ---------------------------------------------------------------------------
// passA: r[i] = sum_j Kd[i,j] * (CSTAR / c[j])
// 256 blocks x 256 thr -> ONE wave (<= 2 blocks/SM). Block = 32 rows:
// warp w sweeps rows 2w,2w+1 then 16+2w,17+2w. Weights in smem (16 KB).
// ---------------------------------------------------------------------------
__global__ void __launch_bounds__(256, 2) k_passA(const float* __restrict__ vin,
                                                  float* __restrict__ vout) {
    __shared__ uint32_t sw[4096];
    const int t = threadIdx.x;
#pragma unroll
    for (int j = 0; j < 8; j++) {
        const int g = t + (j << 8);
        const float4 c4 = *(const float4*)(vin + (g << 2));
        sw[2 * g]     = packh2(__fdividef(CSTAR, c4.x), __fdividef(CSTAR, c4.z));
        sw[2 * g + 1] = packh2(__fdividef(CSTAR, c4.y), __fdividef(CSTAR, c4.w));
    }
    __syncthreads();

    const int w = t >> 5, lane = t & 31;
    const int row0 = blockIdx.x << 5;
    const uint4* swv = ((const uint4*)sw) + (lane << 1);

#pragma unroll
    for (int half = 0; half < 2; half++) {
        const int rowa = row0 + (half << 4) + (w << 1);
        const uint4* base =
            ((const uint4*)g_K8) + (size_t)rowa * (NN / 16) + lane;
        float va, vb;
        sweep2(base, swv, va, vb);
        if (lane == 0) {
            vout[rowa]     = va;
            vout[rowa + 1] = vb;
        }
    }
}

// ---------------------------------------------------------------------------
// passB: c[j] += sum_{i in 64-row group} Kd[i,j] * (CSTAR / r[i])
// grid (2, 128) = 256 blocks -> ONE wave. Block = 64 rows x 4096 cols,
// thread = one uint4 (16 cols) per row; 8-deep batches; flush at 32 rows;
// 16 atomics/thread into the zeroed c slice (128 contributors/address).
// ---------------------------------------------------------------------------
__global__ void __launch_bounds__(256, 2) k_passB(const float* __restrict__ vin,
                                                  float* __restrict__ vout) {
    __shared__ uint32_t swr[64];
    const int t  = threadIdx.x;
    const int r0 = blockIdx.y << 6;
    const int cc = (blockIdx.x << 8) + t;     // uint4 chunk index 0..511
    if (t < 64) {
        const float wv = __fdividef(CSTAR, vin[r0 + t]);
        swr[t] = packh2(wv, wv);
    }
    __syncthreads();

    const uint4* __restrict__ base =
        ((const uint4*)g_K8) + (size_t)r0 * (NN / 16) + cc;

    const __half2 z = __floats2half2_rn(0.f, 0.f);
    __half2 A0 = z, A1 = z, A2 = z, A3 = z;
    __half2 A4 = z, A5 = z, A6 = z, A7 = z;
    float f[16];
#pragma unroll
    for (int j = 0; j < 16; j++) f[j] = 0.0f;

#pragma unroll
    for (int b = 0; b < 8; b++) {
        uint4 q[8];
#pragma unroll
        for (int j = 0; j < 8; j++)
            q[j] = base[(size_t)((b << 3) + j) * (NN / 16)];
#pragma unroll
        for (int j = 0; j < 8; j++) {
            const __half2 wr = u2h(swr[(b << 3) + j]);
            A0 = __hfma2(dE(q[j].x), wr, A0);
            A1 = __hfma2(dO(q[j].x), wr, A1);
            A2 = __hfma2(dE(q[j].y), wr, A2);
            A3 = __hfma2(dO(q[j].y), wr, A3);
            A4 = __hfma2(dE(q[j].z), wr, A4);
            A5 = __hfma2(dO(q[j].z), wr, A5);
            A6 = __hfma2(dE(q[j].w), wr, A6);
            A7 = __hfma2(dO(q[j].w), wr, A7);
        }
        if (b == 3 || b == 7) {   // flush every 32 rows (chain cap = 32)
            f[0]  += __low2float(A0);   f[2]  += __high2float(A0);
            f[1]  += __low2float(A1);   f[3]  += __high2float(A1);
            f[4]  += __low2float(A2);   f[6]  += __high2float(A2);
            f[5]  += __low2float(A3);   f[7]  += __high2float(A3);
            f[8]  += __low2float(A4);   f[10] += __high2float(A4);
            f[9]  += __low2float(A5);   f[11] += __high2float(A5);
            f[12] += __low2float(A6);   f[14] += __high2float(A6);
            f[13] += __low2float(A7);   f[15] += __high2float(A7);
            A0 = z; A1 = z; A2 = z; A3 = z;
            A4 = z; A5 = z; A6 = z; A7 = z;
        }
    }

    float* vo = vout + (cc << 4);
#pragma unroll
    for (int j = 0; j < 16; j++) atomicAdd(vo + j, f[j]);
}

// ---------------------------------------------------------------------------
// loss = -10*S1 + 35*ln2*S3 + <trow, ln r50> + <tcol, ln c50>
// ---------------------------------------------------------------------------
__global__ void __launch_bounds__(1024) k_final(float* __restrict__ out) {
    const int t = threadIdx.x;
    const float* cfin = g_c + (size_t)NITER * NN;
    float s1 = 0.f, s2 = 0.f, s3 = 0.f;
    for (int i = t; i < NN; i += 1024) {
        const float tr = g_trow[i];
        s1 += tr * __logf(g_rf[i]);
        s3 += tr;
        s2 += g_tcol[i] * __logf(cfin[i]);
    }
    __shared__ float sa[1024], sb[1024], sc[1024];
    sa[t] = s1; sb[t] = s2; sc[t] = s3;
    __syncthreads();
    for (int s = 512; s > 0; s >>= 1) {
        if (t < s) { sa[t] += sa[t + s]; sb[t] += sb[t + s]; sc[t] += sc[t + s]; }
        __syncthreads();
    }
    if (t == 0)
        out[0] = -10.0f * g_S1[0] + 24.260151319598086f * sc[0] + sa[0] + sb[0];
}

// ---------------------------------------------------------------------------
extern "C" void kernel_launch(void* const* d_in, const int* in_sizes, int n_in,
                              void* d_out, int out_size) {
    (void)in_sizes; (void)n_in; (void)out_size;
    const float* M   = (const float*)d_in[0];
    const float* tgt = (const float*)d_in[1];
    float* out = (float*)d_out;

    void *pC, *pR;
    cudaGetSymbolAddress(&pC, g_c);
    cudaGetSymbolAddress(&pR, g_rf);
    float* C  = (float*)pC;
    float* RF = (float*)pR;

    k_init<<<1632, 256>>>();
    k_bt<<<dim3(8, 64), 256>>>(M, tgt);

    for (int k = 1; k <= NITER; k++) {
        k_passA<<<256, 256>>>(C + (size_t)(k - 1) * NN, RF);
        k_passB<<<dim3(2, 128), 256>>>(RF, C + (size_t)k * NN);
    }
    k_final<<<1, 1024>>>(out);
}

// round 11
// speedup vs baseline: 2.5936x; 1.0028x over previous
#include <cuda_runtime.h>
#include <cuda_fp16.h>
#include <stdint.h>

#define NN 8192
#define NITER 50
#define CSTAR 0.00390625f   /* 2^-8 */
/* decoded K = K_true * 2^-14; r scaled 2^-22, c unscaled (see k_final) */

static __device__ __align__(256) uint32_t g_K8[(size_t)NN * NN / 4];
static __device__ __align__(16) float g_c[(NITER + 1) * NN];  // atomic slices
static __device__ __align__(16) float g_rf[NN];
static __device__ float g_trow[NN];
static __device__ float g_tcol[NN];
static __device__ float g_S1[1];

static __device__ __forceinline__ __half2 u2h(uint32_t x) {
    return *reinterpret_cast<__half2*>(&x);
}
// two e4m3 bytes (sign=0) -> half2 of value*2^-8, exact (incl. subnormals)
static __device__ __forceinline__ __half2 dE(uint32_t q) {  // bytes 0,2
    return u2h((q << 7) & 0x7F807F80u);
}
static __device__ __forceinline__ __half2 dO(uint32_t q) {  // bytes 1,3
    return u2h((q >> 1) & 0x7F807F80u);
}
static __device__ __forceinline__ float ex2f(float x) {
    float r; asm("ex2.approx.f32 %0, %1;" : "=f"(r) : "f"(x)); return r;
}
static __device__ __forceinline__ uint32_t packh2(float a, float b) {
    const uint32_t ua = __half_as_ushort(__float2half_rn(a));
    const uint32_t ub = __half_as_ushort(__float2half_rn(b));
    return ua | (ub << 16);
}

// ---------------------------------------------------------------------------
__global__ void k_init() {
    const int n = (NITER + 1) * NN;   // 417792 == 1632*256
    for (int i = blockIdx.x * blockDim.x + threadIdx.x; i < n;
         i += gridDim.x * blockDim.x) {
        g_c[i] = (i < NN) ? 1.0f : 0.0f;
        if (i < NN) { g_trow[i] = 0.0f; g_tcol[i] = 0.0f; }
        if (i == 0) g_S1[0] = 0.0f;
    }
}

// ---------------------------------------------------------------------------
// fused build + target reductions (proven)
// ---------------------------------------------------------------------------
__global__ void __launch_bounds__(256) k_bt(const float* __restrict__ M,
                                            const float* __restrict__ tgt) {
    const int r0 = blockIdx.y << 7;
    const int c0 = blockIdx.x << 10;
    const int t  = threadIdx.x;
    const int lane = t & 31;
    const float4* __restrict__ pm =
        (const float4*)(M + (size_t)r0 * NN + c0) + t;
    const float4* __restrict__ pt =
        (const float4*)(tgt + (size_t)r0 * NN + c0) + t;
    uint32_t* __restrict__ pk = g_K8 + (size_t)r0 * (NN / 4) + (c0 >> 2) + t;

    float cx = 0.f, cy = 0.f, cz = 0.f, cw = 0.f, dot = 0.f;
    for (int r = 0; r < 128; r++) {
        const float4 m4 = pm[r * (NN / 4)];
        const float4 t4 = pt[r * (NN / 4)];
        const float e0 = ex2f(fmaf(14.42695041f, m4.x, -6.0f));
        const float e1 = ex2f(fmaf(14.42695041f, m4.y, -6.0f));
        const float e2 = ex2f(fmaf(14.42695041f, m4.z, -6.0f));
        const float e3 = ex2f(fmaf(14.42695041f, m4.w, -6.0f));
        unsigned short lo, hi;
        asm("cvt.rn.satfinite.e4m3x2.f32 %0, %1, %2;" : "=h"(lo) : "f"(e1), "f"(e0));
        asm("cvt.rn.satfinite.e4m3x2.f32 %0, %1, %2;" : "=h"(hi) : "f"(e3), "f"(e2));
        pk[r * (NN / 4)] = (uint32_t)lo | ((uint32_t)hi << 16);

        cx += t4.x; cy += t4.y; cz += t4.z; cw += t4.w;
        dot = fmaf(t4.x, m4.x, dot);
        dot = fmaf(t4.y, m4.y, dot);
        dot = fmaf(t4.z, m4.z, dot);
        dot = fmaf(t4.w, m4.w, dot);
        float s4 = (t4.x + t4.y) + (t4.z + t4.w);
#pragma unroll
        for (int o = 16; o; o >>= 1)
            s4 += __shfl_xor_sync(0xFFFFFFFFu, s4, o);
        if (lane == 0) atomicAdd(&g_trow[r0 + r], s4);
    }
    float* tc = g_tcol + c0 + (t << 2);
    atomicAdd(tc + 0, cx);
    atomicAdd(tc + 1, cy);
    atomicAdd(tc + 2, cz);
    atomicAdd(tc + 3, cw);

    __shared__ float sred[256];
    sred[t] = dot;
    __syncthreads();
    for (int s = 128; s > 0; s >>= 1) {
        if (t < s) sred[t] += sred[t + s];
        __syncthreads();
    }
    if (t == 0) atomicAdd(&g_S1[0], sred[0]);
}

// ---------------------------------------------------------------------------
// two-row dot sweep over full 8192 cols (R7 pattern, proven)
// ---------------------------------------------------------------------------
static __device__ __forceinline__ void sweep2(
    const uint4* __restrict__ base, const uint4* __restrict__ swv,
    float& va, float& vb)
{
    const uint4* pa = base;
    const uint4* pb = base + (NN / 16);
    const __half2 z = __floats2half2_rn(0.f, 0.f);
    __half2 aE0 = z, aO0 = z, aE1 = z, aO1 = z;
    __half2 bE0 = z, bO0 = z, bE1 = z, bO1 = z;

#pragma unroll 2
    for (int s = 0; s < 16; s += 4) {
        uint4 qa[4], qb[4];
#pragma unroll
        for (int j = 0; j < 4; j++) {
            qa[j] = pa[(s + j) * 32];
            qb[j] = pb[(s + j) * 32];
        }
#pragma unroll
        for (int j = 0; j < 4; j++) {
            const uint4 w0 = swv[(s + j) << 6];
            const uint4 w1 = swv[((s + j) << 6) + 1];
            aE0 = __hfma2(dE(qa[j].x), u2h(w0.x), aE0);
            aO0 = __hfma2(dO(qa[j].x), u2h(w0.y), aO0);
            aE1 = __hfma2(dE(qa[j].y), u2h(w0.z), aE1);
            aO1 = __hfma2(dO(qa[j].y), u2h(w0.w), aO1);
            aE0 = __hfma2(dE(qa[j].z), u2h(w1.x), aE0);
            aO0 = __hfma2(dO(qa[j].z), u2h(w1.y), aO0);
            aE1 = __hfma2(dE(qa[j].w), u2h(w1.z), aE1);
            aO1 = __hfma2(dO(qa[j].w), u2h(w1.w), aO1);
            bE0 = __hfma2(dE(qb[j].x), u2h(w0.x), bE0);
            bO0 = __hfma2(dO(qb[j].x), u2h(w0.y), bO0);
            bE1 = __hfma2(dE(qb[j].y), u2h(w0.z), bE1);
            bO1 = __hfma2(dO(qb[j].y), u2h(w0.w), bO1);
            bE0 = __hfma2(dE(qb[j].z), u2h(w1.x), bE0);
            bO0 = __hfma2(dO(qb[j].z), u2h(w1.y), bO0);
            bE1 = __hfma2(dE(qb[j].w), u2h(w1.z), bE1);
            bO1 = __hfma2(dO(qb[j].w), u2h(w1.w), bO1);
        }
    }
    __half2 sa = __hadd2(__hadd2(aE0, aO0), __hadd2(aE1, aO1));
    __half2 sb = __hadd2(__hadd2(bE0, bO0), __hadd2(bE1, bO1));
    va = __low2float(sa) + __high2float(sa);
    vb = __low2float(sb) + __high2float(sb);
#pragma unroll
    for (int o = 16; o; o >>= 1) {
        va += __shfl_xor_sync(0xFFFFFFFFu, va, o);
        vb += __shfl_xor_sync(0xFFFFFFFFu, vb, o);
    }
}

// ---------------------------------------------------------------------------
// passA: r[i] = sum_j Kd[i,j] * (CSTAR / c[j])
// 256 blocks x 256 thr -> ONE wave (<= 2 blocks/SM). Block = 32 rows:
// warp w sweeps rows 2w,2w+1 then 16+2w,17+2w. Weights in smem (16 KB).
// ---------------------------------------------------------------------------
__global__ void __launch_bounds__(256, 2) k_passA(const float* __restrict__ vin,
                                                  float* __restrict__ vout) {
    __shared__ uint32_t sw[4096];
    const int t = threadIdx.x;
#pragma unroll
    for (int j = 0; j < 8; j++) {
        const int g = t + (j << 8);
        const float4 c4 = *(const float4*)(vin + (g << 2));
        sw[2 * g]     = packh2(__fdividef(CSTAR, c4.x), __fdividef(CSTAR, c4.z));
        sw[2 * g + 1] = packh2(__fdividef(CSTAR, c4.y), __fdividef(CSTAR, c4.w));
    }
    __syncthreads();

    const int w = t >> 5, lane = t & 31;
    const int row0 = blockIdx.x << 5;
    const uint4* swv = ((const uint4*)sw) + (lane << 1);

#pragma unroll
    for (int half = 0; half < 2; half++) {
        const int rowa = row0 + (half << 4) + (w << 1);
        const uint4* base =
            ((const uint4*)g_K8) + (size_t)rowa * (NN / 16) + lane;
        float va, vb;
        sweep2(base, swv, va, vb);
        if (lane == 0) {
            vout[rowa]     = va;
            vout[rowa + 1] = vb;
        }
    }
}

// ---------------------------------------------------------------------------
// passB: c[j] += sum_{i in 64-row group} Kd[i,j] * (CSTAR / r[i])
// grid (2, 128) = 256 blocks -> ONE wave. Block = 64 rows x 4096 cols,
// thread = one uint4 (16 cols) per row; 8-deep batches; flush at 32 rows;
// 16 atomics/thread into the zeroed c slice (128 contributors/address).
// ---------------------------------------------------------------------------
__global__ void __launch_bounds__(256, 2) k_passB(const float* __restrict__ vin,
                                                  float* __restrict__ vout) {
    __shared__ uint32_t swr[64];
    const int t  = threadIdx.x;
    const int r0 = blockIdx.y << 6;
    const int cc = (blockIdx.x << 8) + t;     // uint4 chunk index 0..511
    if (t < 64) {
        const float wv = __fdividef(CSTAR, vin[r0 + t]);
        swr[t] = packh2(wv, wv);
    }
    __syncthreads();

    const uint4* __restrict__ base =
        ((const uint4*)g_K8) + (size_t)r0 * (NN / 16) + cc;

    const __half2 z = __floats2half2_rn(0.f, 0.f);
    __half2 A0 = z, A1 = z, A2 = z, A3 = z;
    __half2 A4 = z, A5 = z, A6 = z, A7 = z;
    float f[16];
#pragma unroll
    for (int j = 0; j < 16; j++) f[j] = 0.0f;

#pragma unroll
    for (int b = 0; b < 8; b++) {
        uint4 q[8];
#pragma unroll
        for (int j = 0; j < 8; j++)
            q[j] = base[(size_t)((b << 3) + j) * (NN / 16)];
#pragma unroll
        for (int j = 0; j < 8; j++) {
            const __half2 wr = u2h(swr[(b << 3) + j]);
            A0 = __hfma2(dE(q[j].x), wr, A0);
            A1 = __hfma2(dO(q[j].x), wr, A1);
            A2 = __hfma2(dE(q[j].y), wr, A2);
            A3 = __hfma2(dO(q[j].y), wr, A3);
            A4 = __hfma2(dE(q[j].z), wr, A4);
            A5 = __hfma2(dO(q[j].z), wr, A5);
            A6 = __hfma2(dE(q[j].w), wr, A6);
            A7 = __hfma2(dO(q[j].w), wr, A7);
        }
        if (b == 3 || b == 7) {   // flush every 32 rows (chain cap = 32)
            f[0]  += __low2float(A0);   f[2]  += __high2float(A0);
            f[1]  += __low2float(A1);   f[3]  += __high2float(A1);
            f[4]  += __low2float(A2);   f[6]  += __high2float(A2);
            f[5]  += __low2float(A3);   f[7]  += __high2float(A3);
            f[8]  += __low2float(A4);   f[10] += __high2float(A4);
            f[9]  += __low2float(A5);   f[11] += __high2float(A5);
            f[12] += __low2float(A6);   f[14] += __high2float(A6);
            f[13] += __low2float(A7);   f[15] += __high2float(A7);
            A0 = z; A1 = z; A2 = z; A3 = z;
            A4 = z; A5 = z; A6 = z; A7 = z;
        }
    }

    float* vo = vout + (cc << 4);
#pragma unroll
    for (int j = 0; j < 16; j++) atomicAdd(vo + j, f[j]);
}

// ---------------------------------------------------------------------------
// loss = -10*S1 + 35*ln2*S3 + <trow, ln r50> + <tcol, ln c50>
// ---------------------------------------------------------------------------
__global__ void __launch_bounds__(1024) k_final(float* __restrict__ out) {
    const int t = threadIdx.x;
    const float* cfin = g_c + (size_t)NITER * NN;
    float s1 = 0.f, s2 = 0.f, s3 = 0.f;
    for (int i = t; i < NN; i += 1024) {
        const float tr = g_trow[i];
        s1 += tr * __logf(g_rf[i]);
        s3 += tr;
        s2 += g_tcol[i] * __logf(cfin[i]);
    }
    __shared__ float sa[1024], sb[1024], sc[1024];
    sa[t] = s1; sb[t] = s2; sc[t] = s3;
    __syncthreads();
    for (int s = 512; s > 0; s >>= 1) {
        if (t < s) { sa[t] += sa[t + s]; sb[t] += sb[t + s]; sc[t] += sc[t + s]; }
        __syncthreads();
    }
    if (t == 0)
        out[0] = -10.0f * g_S1[0] + 24.260151319598086f * sc[0] + sa[0] + sb[0];
}

// ---------------------------------------------------------------------------
extern "C" void kernel_launch(void* const* d_in, const int* in_sizes, int n_in,
                              void* d_out, int out_size) {
    (void)in_sizes; (void)n_in; (void)out_size;
    const float* M   = (const float*)d_in[0];
    const float* tgt = (const float*)d_in[1];
    float* out = (float*)d_out;

    void *pC, *pR;
    cudaGetSymbolAddress(&pC, g_c);
    cudaGetSymbolAddress(&pR, g_rf);
    float* C  = (float*)pC;
    float* RF = (float*)pR;

    k_init<<<1632, 256>>>();
    k_bt<<<dim3(8, 64), 256>>>(M, tgt);

    for (int k = 1; k <= NITER; k++) {
        k_passA<<<256, 256>>>(C + (size_t)(k - 1) * NN, RF);
        k_passB<<<dim3(2, 128), 256>>>(RF, C + (size_t)k * NN);
    }
    k_final<<<1, 1024>>>(out);
}